// round 16
// baseline (speedup 1.0000x reference)
#include <cuda_runtime.h>

// ---------------------------------------------------------------------------
// Batch-independent factorization of the collapsed reference:
//   out[b,s,h*64+e] = RV[b,h,e] * beta[b,s,h] * (S_mas[b,s] != 0)
//   beta[b,s,h] = dot(S[b,s,h*64:], W[b,h,:]) + c[b,h]
//   W[b,h,d]  = b0[d]   + sum_d' At[d',d] * r[b,h,d']     At = WQ_w^T WK_w
//   c[b,h]    = c0      + sum_d' u[d']    * r[b,h,d']     u  = WK_w^T WQ_b
//   RV[b,h,e] = WV_b[e] + sum_d  WVt[d,e] * r[b,h,d]      WVt = WV_w^T
//
// Node 1 (weights_kernel, 71 blocks): At/WVt/u/b0/c0 + flag reset.
// Node 2 (stream kernel, 32 regs pinned): y==0 blocks produce their batch's
//   W/RV/c with a SPILL-FREE producer (4-deep chains, shfl+smem reduce,
//   coalesced L1-resident loads -> ~3us window), publish via fence+flag;
//   consumers spin briefly then run the proven 77%-DRAM streaming loop.
// ---------------------------------------------------------------------------

__device__ float g_At [64 * 64];   // [d'][d], d fast
__device__ float g_WVt[64 * 64];   // [d][e],  e fast
__device__ float g_u  [64];
__device__ float g_b0 [64];
__device__ float g_c0;

#define MAX_DPS 64
__device__ float g_W   [MAX_DPS * 1024];
__device__ float g_RV  [MAX_DPS * 1024];
__device__ float g_C   [MAX_DPS * 16];
__device__ int   g_flag[MAX_DPS];

// ---------------------------------------------------------------------------
// weights_kernel: grid 71, block 256.
//  blocks 0..63 : At row d' = g (4-way e-split + smem reduce, coalesced).
//  blocks 64..67: WVt transpose quarter. 68: u. 69: b0. 70: c0 + flags.
// ---------------------------------------------------------------------------
__global__ __launch_bounds__(256) void weights_kernel(
    const float* __restrict__ WQ_w, const float* __restrict__ WQ_b,
    const float* __restrict__ WK_w, const float* __restrict__ WK_b,
    const float* __restrict__ WV_w) {
    const int g = blockIdx.x;
    const int t = threadIdx.x;
    __shared__ float red[256];

    if (g < 64) {
        const int d    = t & 63;
        const int part = t >> 6;
        float acc = 0.f;
#pragma unroll 16
        for (int i = 0; i < 16; i++) {
            const int e = part * 16 + i;
            acc = fmaf(WQ_w[e * 64 + d], WK_w[e * 64 + g], acc);
        }
        red[t] = acc;
        __syncthreads();
        if (part == 0)
            g_At[g * 64 + d] = acc + red[d + 64] + red[d + 128] + red[d + 192];
    } else if (g < 68) {
        const int k = g - 64;
#pragma unroll
        for (int i = 0; i < 4; i++) {
            const int idx = k * 1024 + i * 256 + t;
            const int d = idx >> 6, e = idx & 63;
            g_WVt[d * 64 + e] = WV_w[e * 64 + d];
        }
    } else if (g == 68) {
        const int dp   = t & 63;
        const int part = t >> 6;
        float acc = 0.f;
#pragma unroll 16
        for (int i = 0; i < 16; i++) {
            const int e = part * 16 + i;
            acc = fmaf(WQ_b[e], WK_w[e * 64 + dp], acc);
        }
        red[t] = acc;
        __syncthreads();
        if (part == 0)
            g_u[dp] = acc + red[dp + 64] + red[dp + 128] + red[dp + 192];
    } else if (g == 69) {
        const int d    = t & 63;
        const int part = t >> 6;
        float acc = 0.f;
#pragma unroll 16
        for (int i = 0; i < 16; i++) {
            const int e = part * 16 + i;
            acc = fmaf(WQ_w[e * 64 + d], WK_b[e], acc);
        }
        red[t] = acc;
        __syncthreads();
        if (part == 0)
            g_b0[d] = acc + red[d + 64] + red[d + 128] + red[d + 192];
    } else {
        if (t < MAX_DPS) g_flag[t] = 0;    // replay-safe flag reset
        if (t == 0) {
            float a0 = 0.f, a1 = 0.f, a2 = 0.f, a3 = 0.f;
#pragma unroll 4
            for (int e = 0; e < 64; e += 4) {
                a0 = fmaf(WQ_b[e + 0], WK_b[e + 0], a0);
                a1 = fmaf(WQ_b[e + 1], WK_b[e + 1], a1);
                a2 = fmaf(WQ_b[e + 2], WK_b[e + 2], a2);
                a3 = fmaf(WQ_b[e + 3], WK_b[e + 3], a3);
            }
            g_c0 = (a0 + a1) + (a2 + a3);
        }
    }
}

// ---------------------------------------------------------------------------
// stream kernel: producer handshake with a spill-free producer.
// Producer thread t -> (q = t&15 output-quad, rep = t>>4 over 16 d'-chunks
// of 4). Per head: 8 coalesced LDG.128 (At/WVt, L1-resident after round 1),
// 4-deep chains, shfl_xor(16) pair-combine, 8-warp smem reduce. 16 rounds.
// ---------------------------------------------------------------------------
template <int ROWS_PER_BLOCK, int UNROLL>
__global__ __launch_bounds__(256, 8) void stream_kernel(
    const float* __restrict__ S,
    const float* __restrict__ R,
    const int*   __restrict__ S_mas,
    const float* __restrict__ WV_b,
    float*       __restrict__ out,
    int seq) {
    const int b = blockIdx.x;
    const int t = threadIdx.x;

    if (blockIdx.y == 0) {
        // ---- Producer: compute W/RV/c for batch b ----
        __shared__ float  r_s[1024];
        __shared__ float4 redw[8][16];
        __shared__ float4 redv[8][16];
        __shared__ float  redc[8];

#pragma unroll
        for (int i = 0; i < 4; i++)
            r_s[i * 256 + t] = R[b * 1024 + i * 256 + t];
        __syncthreads();

        const int w   = t >> 5;
        const int q   = t & 15;
        const int rep = t >> 4;            // 0..15
        const float4* At4 = reinterpret_cast<const float4*>(g_At);
        const float4* Vt4 = reinterpret_cast<const float4*>(g_WVt);

        for (int h = 0; h < 16; h++) {
            const float* rh = r_s + h * 64;
            float4 wq = {0, 0, 0, 0}, vq = {0, 0, 0, 0};
            float  cc = 0.f;
#pragma unroll
            for (int i = 0; i < 4; i++) {
                const int   dp = rep * 4 + i;
                const float rr = rh[dp];            // half-warp broadcast LDS
                const float4 a4 = At4[dp * 16 + q]; // coalesced 256B segment
                wq.x = fmaf(a4.x, rr, wq.x); wq.y = fmaf(a4.y, rr, wq.y);
                wq.z = fmaf(a4.z, rr, wq.z); wq.w = fmaf(a4.w, rr, wq.w);
                const float4 v4 = Vt4[dp * 16 + q];
                vq.x = fmaf(v4.x, rr, vq.x); vq.y = fmaf(v4.y, rr, vq.y);
                vq.z = fmaf(v4.z, rr, vq.z); vq.w = fmaf(v4.w, rr, vq.w);
                cc = fmaf(g_u[dp], rr, cc);         // uniform
            }
            // combine rep pairs: lanes l and l^16 share q
            wq.x += __shfl_xor_sync(0xffffffffu, wq.x, 16);
            wq.y += __shfl_xor_sync(0xffffffffu, wq.y, 16);
            wq.z += __shfl_xor_sync(0xffffffffu, wq.z, 16);
            wq.w += __shfl_xor_sync(0xffffffffu, wq.w, 16);
            vq.x += __shfl_xor_sync(0xffffffffu, vq.x, 16);
            vq.y += __shfl_xor_sync(0xffffffffu, vq.y, 16);
            vq.z += __shfl_xor_sync(0xffffffffu, vq.z, 16);
            vq.w += __shfl_xor_sync(0xffffffffu, vq.w, 16);
            cc   += __shfl_xor_sync(0xffffffffu, cc,   16);
            if ((t & 16) == 0) {
                redw[w][q] = wq;
                redv[w][q] = vq;
                if (q == 0) redc[w] = cc;
            }
            __syncthreads();
            if (t < 16) {
                float4 a = redw[0][t];
#pragma unroll
                for (int k = 1; k < 8; k++) {
                    a.x += redw[k][t].x; a.y += redw[k][t].y;
                    a.z += redw[k][t].z; a.w += redw[k][t].w;
                }
                const float4 b0q = reinterpret_cast<const float4*>(g_b0)[t];
                reinterpret_cast<float4*>(g_W + b * 1024 + h * 64)[t] =
                    make_float4(a.x + b0q.x, a.y + b0q.y,
                                a.z + b0q.z, a.w + b0q.w);
            } else if (t < 32) {
                const int qq = t - 16;
                float4 a = redv[0][qq];
#pragma unroll
                for (int k = 1; k < 8; k++) {
                    a.x += redv[k][qq].x; a.y += redv[k][qq].y;
                    a.z += redv[k][qq].z; a.w += redv[k][qq].w;
                }
                const float4 vbq = reinterpret_cast<const float4*>(WV_b)[qq];
                reinterpret_cast<float4*>(g_RV + b * 1024 + h * 64)[qq] =
                    make_float4(a.x + vbq.x, a.y + vbq.y,
                                a.z + vbq.z, a.w + vbq.w);
            } else if (t == 32) {
                float s = redc[0] + redc[1] + redc[2] + redc[3] +
                          redc[4] + redc[5] + redc[6] + redc[7];
                g_C[b * 16 + h] = s + g_c0;
            }
            __syncthreads();
        }
        __threadfence();       // all writers order their STGs
        __syncthreads();
        if (t == 0) *((volatile int*)&g_flag[b]) = 1;
    } else {
        // ---- Consumer: wait for batch b's constants ----
        if (t == 0) {
            volatile int* f = &g_flag[b];
            while (*f == 0) __nanosleep(64);
        }
        __syncthreads();
        __threadfence();
    }

    // ---- Per-thread stream constants (L2, bypass possibly-stale L1) ----
    const int h = t >> 4;
    const float4 w4  = __ldcg(reinterpret_cast<const float4*>(g_W  + b * 1024) + t);
    const float4 rv4 = __ldcg(reinterpret_cast<const float4*>(g_RV + b * 1024) + t);
    const float  c   = __ldcg(g_C + b * 16 + h);

    // ---- Streaming pass (proven ~80us / 77% DRAM configuration) ----
    const int row0 = blockIdx.y * ROWS_PER_BLOCK;
    const float4* Sp = reinterpret_cast<const float4*>(S) + (size_t)b * seq * 256;
    float4*       Op = reinterpret_cast<float4*>(out)     + (size_t)b * seq * 256;
    const int*    mp = S_mas + (size_t)b * seq;

    const int row_end = (row0 + ROWS_PER_BLOCK < seq) ? row0 + ROWS_PER_BLOCK : seq;

    int r = row0;
    for (; r + UNROLL <= row_end; r += UNROLL) {
        float4 s[UNROLL];
        int    m[UNROLL];
#pragma unroll
        for (int u = 0; u < UNROLL; u++) {
            s[u] = Sp[(size_t)(r + u) * 256 + t];
            m[u] = mp[r + u];
        }
#pragma unroll
        for (int u = 0; u < UNROLL; u++) {
            float p = s[u].x * w4.x + s[u].y * w4.y + s[u].z * w4.z + s[u].w * w4.w;
            p += __shfl_xor_sync(0xffffffffu, p, 8, 16);
            p += __shfl_xor_sync(0xffffffffu, p, 4, 16);
            p += __shfl_xor_sync(0xffffffffu, p, 2, 16);
            p += __shfl_xor_sync(0xffffffffu, p, 1, 16);
            const float beta = (p + c) * (m[u] != 0 ? 1.0f : 0.0f);
            float4 o;
            o.x = rv4.x * beta;
            o.y = rv4.y * beta;
            o.z = rv4.z * beta;
            o.w = rv4.w * beta;
            Op[(size_t)(r + u) * 256 + t] = o;
        }
    }
    for (; r < row_end; r++) {
        float4 s = Sp[(size_t)r * 256 + t];
        int    m = mp[r];
        float p = s.x * w4.x + s.y * w4.y + s.z * w4.z + s.w * w4.w;
        p += __shfl_xor_sync(0xffffffffu, p, 8, 16);
        p += __shfl_xor_sync(0xffffffffu, p, 4, 16);
        p += __shfl_xor_sync(0xffffffffu, p, 2, 16);
        p += __shfl_xor_sync(0xffffffffu, p, 1, 16);
        const float beta = (p + c) * (m != 0 ? 1.0f : 0.0f);
        float4 o;
        o.x = rv4.x * beta;
        o.y = rv4.y * beta;
        o.z = rv4.z * beta;
        o.w = rv4.w * beta;
        Op[(size_t)r * 256 + t] = o;
    }
}

// ---------------------------------------------------------------------------
// Launch. Inputs (metadata order):
//   0 S (dps,seq,1024) f32   1 R (dps,1,1024) f32
//   2 S_mas (dps,seq,1) i32  3 R_mas (dps,1,1) i32 (dead)
//   4 WQ_w  5 WQ_b  6 WK_w  7 WK_b  8 WV_w  9 WV_b
// ---------------------------------------------------------------------------
extern "C" void kernel_launch(void* const* d_in, const int* in_sizes, int n_in,
                              void* d_out, int out_size) {
    const float* S     = (const float*)d_in[0];
    const float* R     = (const float*)d_in[1];
    const int*   S_mas = (const int*)  d_in[2];
    const float* WQ_w  = (const float*)d_in[4];
    const float* WQ_b  = (const float*)d_in[5];
    const float* WK_w  = (const float*)d_in[6];
    const float* WK_b  = (const float*)d_in[7];
    const float* WV_w  = (const float*)d_in[8];
    const float* WV_b  = (const float*)d_in[9];
    float* out = (float*)d_out;

    int dps = in_sizes[1] / 1024;          // R element count = dps*1024
    if (dps > MAX_DPS) dps = MAX_DPS;
    int seq = in_sizes[0] / (dps * 1024);  // S element count = dps*seq*1024

    weights_kernel<<<71, 256>>>(WQ_w, WQ_b, WK_w, WK_b, WV_w);

    constexpr int ROWS   = 64;
    constexpr int UNROLL = 4;
    int nblk = (seq + ROWS - 1) / ROWS;
    stream_kernel<ROWS, UNROLL><<<dim3(dps, nblk), 256>>>(
        S, R, S_mas, WV_b, out, seq);
}

// round 17
// speedup vs baseline: 1.1604x; 1.1604x over previous
#include <cuda_runtime.h>

// ---------------------------------------------------------------------------
// Collapsed reference:
//   out[b,s,h*64+e] = RV[b,h,e] * beta[b,s,h] * (S_mas[b,s] != 0)
//   beta[b,s,h] = dot(S[b,s,h*64:], W[b,h,:]) + c[b,h]
//   R_K[e] = WK_b[e] + sum_d WK_w[e,d]*r[d]      (r = R[b, h*64:+64])
//   RV[e]  = WV_b[e] + sum_d WV_w[e,d]*r[d]
//   W[d]   = sum_e WQ_w[e,d]*R_K[e],   c = sum_e WQ_b[e]*R_K[e]
//
// Node 1: precompute_kernel, grid (dps,16) = 512 blocks, ONE (b,h) per
//   block, two short phases (~1us critical path), no inter-node weight
//   factorization. 512-way parallelism hides all cold latencies.
// Node 2: the proven ~80.5us / 77%-DRAM streaming kernel, untouched.
// ---------------------------------------------------------------------------

#define MAX_DPS 64

__device__ float g_W [MAX_DPS * 1024];
__device__ float g_RV[MAX_DPS * 1024];
__device__ float g_C [MAX_DPS * 16];

// ---------------------------------------------------------------------------
// precompute_kernel: one block per (batch, head). block 256.
// Phase A (thread = (e = t>>2, part = t&3)): R_K[e], RV[e] partials over
//   d in part*16..+16 via 4 float4 row-loads each of WK/WV (row-major,
//   warp covers 8 rows x 4 slots -> dense 2KB region); combine parts with
//   shfl_xor(1,2); part==0 lane adds bias, writes rk_s / g_RV.
// Phase B (thread = (q = t&15 d-quad, rep = t>>4)): W-quad partial over
//   e in rep*4..+4 via WQ_w float4 reads (16 lanes = full 256B row,
//   2 rows/warp contiguous); c folded in; shfl_xor(16) + 8-warp smem
//   reduce; threads 0..15 write g_W quads, thread 16 writes g_C.
// ---------------------------------------------------------------------------
__global__ __launch_bounds__(256) void precompute_kernel(
    const float* __restrict__ R,
    const float* __restrict__ WQ_w, const float* __restrict__ WQ_b,
    const float* __restrict__ WK_w, const float* __restrict__ WK_b,
    const float* __restrict__ WV_w, const float* __restrict__ WV_b) {
    const int b = blockIdx.x;
    const int h = blockIdx.y;
    const int t = threadIdx.x;

    __shared__ float  r_s [64];
    __shared__ float  rk_s[64];
    __shared__ float4 redw[8][16];
    __shared__ float  redc[8];

    if (t < 64) r_s[t] = R[b * 1024 + h * 64 + t];
    __syncthreads();

    // ---- Phase A: R_K[e], RV[e] ----
    {
        const int e    = t >> 2;       // 0..63
        const int part = t & 3;        // d-range part*16..+16
        const float4* wk4 = reinterpret_cast<const float4*>(WK_w) + e * 16 + part * 4;
        const float4* wv4 = reinterpret_cast<const float4*>(WV_w) + e * 16 + part * 4;
        const float*  rp  = r_s + part * 16;

        float rk = 0.f, rv = 0.f;
#pragma unroll
        for (int j = 0; j < 4; j++) {
            const float4 k4 = wk4[j];
            const float4 v4 = wv4[j];
            const float r0 = rp[j * 4 + 0], r1 = rp[j * 4 + 1];
            const float r2 = rp[j * 4 + 2], r3 = rp[j * 4 + 3];
            rk = fmaf(k4.x, r0, rk); rk = fmaf(k4.y, r1, rk);
            rk = fmaf(k4.z, r2, rk); rk = fmaf(k4.w, r3, rk);
            rv = fmaf(v4.x, r0, rv); rv = fmaf(v4.y, r1, rv);
            rv = fmaf(v4.z, r2, rv); rv = fmaf(v4.w, r3, rv);
        }
        // combine the 4 parts (adjacent lanes)
        rk += __shfl_xor_sync(0xffffffffu, rk, 1);
        rk += __shfl_xor_sync(0xffffffffu, rk, 2);
        rv += __shfl_xor_sync(0xffffffffu, rv, 1);
        rv += __shfl_xor_sync(0xffffffffu, rv, 2);
        if (part == 0) {
            rk_s[e] = rk + WK_b[e];
            g_RV[b * 1024 + h * 64 + e] = rv + WV_b[e];
        }
    }
    __syncthreads();

    // ---- Phase B: W[d] quads + c ----
    {
        const int q   = t & 15;        // d-quad
        const int rep = t >> 4;        // e-range rep*4..+4
        const int w   = t >> 5;
        const float4* wq4 = reinterpret_cast<const float4*>(WQ_w);

        float4 acc = {0.f, 0.f, 0.f, 0.f};
        float  cc  = 0.f;
#pragma unroll
        for (int i = 0; i < 4; i++) {
            const int   e   = rep * 4 + i;
            const float rke = rk_s[e];                 // half-warp broadcast
            const float4 q4 = wq4[e * 16 + q];         // 256B/row coalesced
            acc.x = fmaf(q4.x, rke, acc.x);
            acc.y = fmaf(q4.y, rke, acc.y);
            acc.z = fmaf(q4.z, rke, acc.z);
            acc.w = fmaf(q4.w, rke, acc.w);
            cc = fmaf(WQ_b[e], rke, cc);               // uniform
        }
        // combine rep pairs (lanes l, l^16 share q)
        acc.x += __shfl_xor_sync(0xffffffffu, acc.x, 16);
        acc.y += __shfl_xor_sync(0xffffffffu, acc.y, 16);
        acc.z += __shfl_xor_sync(0xffffffffu, acc.z, 16);
        acc.w += __shfl_xor_sync(0xffffffffu, acc.w, 16);
        cc    += __shfl_xor_sync(0xffffffffu, cc,    16);
        if ((t & 16) == 0) {
            redw[w][q] = acc;
            if (q == 0) redc[w] = cc;
        }
        __syncthreads();
        if (t < 16) {
            float4 a = redw[0][t];
#pragma unroll
            for (int k = 1; k < 8; k++) {
                a.x += redw[k][t].x; a.y += redw[k][t].y;
                a.z += redw[k][t].z; a.w += redw[k][t].w;
            }
            reinterpret_cast<float4*>(g_W + b * 1024 + h * 64)[t] = a;
        } else if (t == 16) {
            float s = redc[0] + redc[1] + redc[2] + redc[3] +
                      redc[4] + redc[5] + redc[6] + redc[7];
            g_C[b * 16 + h] = s;
        }
    }
}

// ---------------------------------------------------------------------------
// stream_kernel: the proven ~80.5us / 77%-DRAM configuration, untouched.
// grid (dps, seq/ROWS), block 256. Thread owns one float4 of the row;
// head = 16 lanes; dot reduced with shfl.xor width=16.
// ---------------------------------------------------------------------------
template <int ROWS_PER_BLOCK, int UNROLL>
__global__ __launch_bounds__(256) void stream_kernel(
    const float* __restrict__ S,
    const int*   __restrict__ S_mas,
    float*       __restrict__ out,
    int seq) {
    const int b   = blockIdx.x;
    const int tid = threadIdx.x;      // 0..255
    const int h   = tid >> 4;         // head = 16 consecutive lanes

    const float4 w  = reinterpret_cast<const float4*>(g_W  + b * 1024)[tid];
    const float4 rv = reinterpret_cast<const float4*>(g_RV + b * 1024)[tid];
    const float  c  = g_C[b * 16 + h];

    const int row0 = blockIdx.y * ROWS_PER_BLOCK;
    const float4* Sp = reinterpret_cast<const float4*>(S) + (size_t)b * seq * 256;
    float4*       Op = reinterpret_cast<float4*>(out)     + (size_t)b * seq * 256;
    const int*    mp = S_mas + (size_t)b * seq;

    const int row_end = (row0 + ROWS_PER_BLOCK < seq) ? row0 + ROWS_PER_BLOCK : seq;

    int r = row0;
    for (; r + UNROLL <= row_end; r += UNROLL) {
        float4 s[UNROLL];
        int    m[UNROLL];
#pragma unroll
        for (int u = 0; u < UNROLL; u++) {
            s[u] = Sp[(size_t)(r + u) * 256 + tid];
            m[u] = mp[r + u];
        }
#pragma unroll
        for (int u = 0; u < UNROLL; u++) {
            float p = s[u].x * w.x + s[u].y * w.y + s[u].z * w.z + s[u].w * w.w;
            p += __shfl_xor_sync(0xffffffffu, p, 8, 16);
            p += __shfl_xor_sync(0xffffffffu, p, 4, 16);
            p += __shfl_xor_sync(0xffffffffu, p, 2, 16);
            p += __shfl_xor_sync(0xffffffffu, p, 1, 16);
            const float beta = (p + c) * (m[u] != 0 ? 1.0f : 0.0f);
            float4 o;
            o.x = rv.x * beta;
            o.y = rv.y * beta;
            o.z = rv.z * beta;
            o.w = rv.w * beta;
            Op[(size_t)(r + u) * 256 + tid] = o;
        }
    }
    for (; r < row_end; r++) {
        float4 s = Sp[(size_t)r * 256 + tid];
        int    m = mp[r];
        float p = s.x * w.x + s.y * w.y + s.z * w.z + s.w * w.w;
        p += __shfl_xor_sync(0xffffffffu, p, 8, 16);
        p += __shfl_xor_sync(0xffffffffu, p, 4, 16);
        p += __shfl_xor_sync(0xffffffffu, p, 2, 16);
        p += __shfl_xor_sync(0xffffffffu, p, 1, 16);
        const float beta = (p + c) * (m != 0 ? 1.0f : 0.0f);
        float4 o;
        o.x = rv.x * beta;
        o.y = rv.y * beta;
        o.z = rv.z * beta;
        o.w = rv.w * beta;
        Op[(size_t)r * 256 + tid] = o;
    }
}

// ---------------------------------------------------------------------------
// Launch. Inputs (metadata order):
//   0 S (dps,seq,1024) f32   1 R (dps,1,1024) f32
//   2 S_mas (dps,seq,1) i32  3 R_mas (dps,1,1) i32 (dead)
//   4 WQ_w  5 WQ_b  6 WK_w  7 WK_b  8 WV_w  9 WV_b
// ---------------------------------------------------------------------------
extern "C" void kernel_launch(void* const* d_in, const int* in_sizes, int n_in,
                              void* d_out, int out_size) {
    const float* S     = (const float*)d_in[0];
    const float* R     = (const float*)d_in[1];
    const int*   S_mas = (const int*)  d_in[2];
    const float* WQ_w  = (const float*)d_in[4];
    const float* WQ_b  = (const float*)d_in[5];
    const float* WK_w  = (const float*)d_in[6];
    const float* WK_b  = (const float*)d_in[7];
    const float* WV_w  = (const float*)d_in[8];
    const float* WV_b  = (const float*)d_in[9];
    float* out = (float*)d_out;

    int dps = in_sizes[1] / 1024;          // R element count = dps*1024
    if (dps > MAX_DPS) dps = MAX_DPS;
    int seq = in_sizes[0] / (dps * 1024);  // S element count = dps*seq*1024

    precompute_kernel<<<dim3(dps, 16), 256>>>(R, WQ_w, WQ_b, WK_w, WK_b,
                                              WV_w, WV_b);

    constexpr int ROWS   = 64;
    constexpr int UNROLL = 4;
    int nblk = (seq + ROWS - 1) / ROWS;
    stream_kernel<ROWS, UNROLL><<<dim3(dps, nblk), 256>>>(S, S_mas, out, seq);
}